// round 16
// baseline (speedup 1.0000x reference)
#include <cuda_runtime.h>
#include <cuda_fp16.h>
#include <cstdint>

// ---------------- problem constants ----------------
#define K_CODES   1024
#define D_DIM     128
#define N_TOK     65536        // 64 * 32 * 32 tokens (BHWC order)
#define Z_ELEMS   8388608      // 64 * 128 * 32 * 32
#define EMA       0.99f
#define EPSV      1e-5f
#define EPS_FLAG  0.08f        // approx-gap threshold (4.2 sigma of fp16 pair error)

// ---------------- output layout (flattened reference tuple, fp32) ----------------
#define Q_OFF     0
#define IDX_OFF   8388608
#define L_OFF     8454144
#define CB_OFF    8454146
#define CNT_OFF   8585218
#define EMW_OFF   8586242

// ---------------- smem layout for argmin (bytes) ----------------
#define SM_A      0            // 32KB: A fp16 frag-packed (filled in-kernel)
#define SM_B      32768        // 2 stages * 16KB (also fp32 z staging at start)
#define SM_CN     65536        // 1024 floats
#define SM_REDV   69632
#define SM_REDI   70656
#define SM_RED2   71680
#define SM_FT     72704        // 128 ints: flagged local token ids
#define SM_FP     73216        // 128 ints: flagged positions in g_fixlist
#define SM_NF     73728        // 1 int
#define SM_TOTAL  73856
#define ZT_STRIDE 132

// ---------------- smem layout for fixup (bytes, dynamic) ----------------
#define FIX_G     64
#define FX_Z      0            // 64 tokens * 128 floats = 32768
#define FX_C      32768        // 32 codes * 33 float4 = 16896
#define FX_N      49664        // 32 floats
#define FX_TOTAL  49792

// ---------------- global scratch ----------------
__device__ uint32_t g_Bh[65536];          // cb fp16 [tile16][s8][np4][lane32][comp4] (256KB)
__device__ float    g_cnorm[K_CODES];
__device__ float    g_counts[K_CODES];
__device__ float    g_dw[K_CODES * D_DIM];
__device__ int      g_idx[N_TOK];
__device__ float    g_loss;
__device__ float    g_weights[K_CODES];
__device__ int      g_fixcnt;
__device__ int      g_fixlist[N_TOK];
__device__ unsigned long long g_fixkey[N_TOK];   // (ordered-dist << 32) | code
__device__ float    g_zfix[N_TOK * D_DIM];       // compact z rows of flagged tokens

// ---------------- helpers ----------------
__device__ __forceinline__ uint32_t smem_u32(const void* p) {
    uint32_t a;
    asm("{ .reg .u64 t; cvta.to.shared.u64 t, %1; cvt.u32.u64 %0, t; }" : "=r"(a) : "l"(p));
    return a;
}
__device__ __forceinline__ uint32_t packh(float a, float b) {
    __half2 t = __floats2half2_rn(a, b);   // x=a (low), y=b (high)
    return *(uint32_t*)&t;
}
__device__ __forceinline__ void mma16(float* c, const uint32_t* a, const uint32_t* b) {
    asm volatile("mma.sync.aligned.m16n8k16.row.col.f32.f16.f16.f32 "
                 "{%0,%1,%2,%3}, {%4,%5,%6,%7}, {%8,%9}, {%0,%1,%2,%3};"
                 : "+f"(c[0]), "+f"(c[1]), "+f"(c[2]), "+f"(c[3])
                 : "r"(a[0]), "r"(a[1]), "r"(a[2]), "r"(a[3]), "r"(b[0]), "r"(b[1]));
}
// screen merge: no index tie-break (exact ties => gap 0 => flagged => fixup decides)
__device__ __forceinline__ void merge3(float& b1, int& i1, float& b2, float v, int id) {
    if (v < b1) { b2 = b1; b1 = v; i1 = id; }
    else if (v < b2) b2 = v;
}
// order-preserving float -> uint32 (monotone for all finite values)
__device__ __forceinline__ uint32_t fkey(float f) {
    uint32_t b = __float_as_uint(f);
    return (b & 0x80000000u) ? ~b : (b | 0x80000000u);
}
#define CP16(dst, src) \
    asm volatile("cp.async.cg.shared.global [%0], [%1], 16;" :: "r"(dst), "l"(src) : "memory")
#define CP_COMMIT() asm volatile("cp.async.commit_group;" ::: "memory")
#define CP_WAIT1()  asm volatile("cp.async.wait_group 1;" ::: "memory")
#define CP_WAIT0()  asm volatile("cp.async.wait_group 0;" ::: "memory")

// ---------------- fused prep: zero + cnorm + fp16 cb fragments ----------------
__global__ void __launch_bounds__(128) prep_all_kernel(const float* __restrict__ cb) {
    const int k = blockIdx.x, d = threadIdx.x;
    float v = cb[k * D_DIM + d];

    g_dw[k * D_DIM + d] = 0.f;
    if (d == 0) g_counts[k] = 0.f;
    if (k == 0 && d == 0) { g_loss = 0.f; g_fixcnt = 0; }

    float vn = __shfl_xor_sync(0xffffffffu, v, 1);

    float sq = v * v;
    #pragma unroll
    for (int o = 16; o; o >>= 1) sq += __shfl_xor_sync(0xffffffffu, sq, o);
    __shared__ float ws[4];
    if ((d & 31) == 0) ws[d >> 5] = sq;
    __syncthreads();
    if (d == 0) g_cnorm[k] = ws[0] + ws[1] + ws[2] + ws[3];

    if ((d & 1) == 0) {
        uint32_t ph = packh(v, vn);
        int tile = k >> 6, c = k & 63;
        int nf = c >> 3, np = nf >> 1, nin = c & 7;
        int s  = d >> 4, dk = d & 15;
        int kb = dk >> 3, lq = (dk & 7) >> 1;
        int lane = nin * 4 + lq;
        int comp = (nf & 1) * 2 + kb;
        g_Bh[(((tile * 8 + s) * 4 + np) * 32 + lane) * 4 + comp] = ph;
    }
}

// ---------------- fp16 screening GEMM + argmin + fused flagged-z gather ----------------
__global__ void __launch_bounds__(256, 2) argmin_mma_kernel(const float* __restrict__ z) {
    extern __shared__ char smem[];
    const uint32_t smb = smem_u32(smem);
    const int tid = threadIdx.x;
    const int l   = tid & 31, w = tid >> 5;
    const int wr  = w & 3,    wc = w >> 2;
    const int lq  = l & 3,    lr = l >> 2;
    const int ctaM = blockIdx.x;
    const int b   = ctaM >> 3;
    const int s0  = (ctaM & 7) << 7;

    if (tid == 0) *(int*)(smem + SM_NF) = 0;

    // ---- convert z tile -> fp16 A fragments (4 chunks of 32 d, staged in SM_B) ----
    {
        float* zstage = (float*)(smem + SM_B);           // [32 d][ZT_STRIDE]
        const float* zp = z + (size_t)b * 131072 + s0;
        uint4* Adst = (uint4*)(smem + SM_A);
        #pragma unroll
        for (int c = 0; c < 4; c++) {
            #pragma unroll
            for (int j = 0; j < 4; j++) {
                int u = j * 256 + tid;
                int d = u >> 5, t4 = (u & 31) << 2;
                float4 v = *(const float4*)&zp[(size_t)(c * 32 + d) * 1024 + t4];
                *(float4*)&zstage[d * ZT_STRIDE + t4] = v;
            }
            __syncthreads();
            #pragma unroll
            for (int j = 0; j < 2; j++) {
                int u = j * 256 + tid;
                int f = u >> 6, shalf = (u >> 5) & 1, li = u & 31;
                int s = c * 2 + shalf;
                int T0 = f * 16 + (li >> 2);
                int r0 = shalf * 16 + (li & 3) * 2;
                uint32_t rh[4];
                rh[0] = packh(zstage[r0 * ZT_STRIDE + T0],       zstage[(r0 + 1) * ZT_STRIDE + T0]);
                rh[1] = packh(zstage[r0 * ZT_STRIDE + T0 + 8],   zstage[(r0 + 1) * ZT_STRIDE + T0 + 8]);
                rh[2] = packh(zstage[(r0 + 8) * ZT_STRIDE + T0], zstage[(r0 + 9) * ZT_STRIDE + T0]);
                rh[3] = packh(zstage[(r0 + 8) * ZT_STRIDE + T0 + 8], zstage[(r0 + 9) * ZT_STRIDE + T0 + 8]);
                Adst[(f * 8 + s) * 32 + li] = make_uint4(rh[0], rh[1], rh[2], rh[3]);
            }
            __syncthreads();
        }
    }

    {
        CP16(smb + SM_CN + tid * 16, g_cnorm + tid * 4);
        const uint4* bh = (const uint4*)g_Bh;
        #pragma unroll
        for (int j = 0; j < 4; j++) {
            int c = j * 256 + tid;
            CP16(smb + SM_B + c * 16, bh + c);
        }
        CP_COMMIT();
    }

    float acc[2][4][4];
    float best [2][2] = {{3.4e38f, 3.4e38f}, {3.4e38f, 3.4e38f}};
    float best2[2][2] = {{3.4e38f, 3.4e38f}, {3.4e38f, 3.4e38f}};
    int   bidx [2][2] = {{0, 0}, {0, 0}};

    for (int t = 0; t < 16; t++) {
        if (t < 15) {
            const uint4* bh = (const uint4*)g_Bh + (t + 1) * 1024;
            uint32_t dst = smb + SM_B + ((t + 1) & 1) * 16384;
            #pragma unroll
            for (int j = 0; j < 4; j++) {
                int c = j * 256 + tid;
                CP16(dst + c * 16, bh + c);
            }
            CP_COMMIT();
            CP_WAIT1();
        } else {
            CP_WAIT0();
        }
        __syncthreads();

        #pragma unroll
        for (int m = 0; m < 2; m++)
            #pragma unroll
            for (int n = 0; n < 4; n++)
                #pragma unroll
                for (int e = 0; e < 4; e++) acc[m][n][e] = 0.f;

        const uint4* Ah4 = (const uint4*)(smem + SM_A);
        const uint4* Bh4 = (const uint4*)(smem + SM_B + (size_t)(t & 1) * 16384);

        #pragma unroll
        for (int s = 0; s < 8; s++) {
            uint4 A0 = Ah4[((wr * 2 + 0) * 8 + s) * 32 + l];
            uint4 A1 = Ah4[((wr * 2 + 1) * 8 + s) * 32 + l];
            uint4 B0 = Bh4[(s * 4 + wc * 2 + 0) * 32 + l];
            uint4 B1 = Bh4[(s * 4 + wc * 2 + 1) * 32 + l];

            uint32_t ah[2][4] = {{A0.x, A0.y, A0.z, A0.w}, {A1.x, A1.y, A1.z, A1.w}};
            uint32_t bh[4][2] = {{B0.x, B0.y}, {B0.z, B0.w}, {B1.x, B1.y}, {B1.z, B1.w}};

            #pragma unroll
            for (int m = 0; m < 2; m++)
                #pragma unroll
                for (int n = 0; n < 4; n++) mma16(acc[m][n], ah[m], bh[n]);
        }

        const float* cn = (const float*)(smem + SM_CN);
        #pragma unroll
        for (int m = 0; m < 2; m++)
            #pragma unroll
            for (int n = 0; n < 4; n++)
                #pragma unroll
                for (int e = 0; e < 4; e++) {
                    int code = t * 64 + (wc * 4 + n) * 8 + lq * 2 + (e & 1);
                    float dist = fmaf(-2.f, acc[m][n][e], cn[code]);
                    int rb = e >> 1;
                    merge3(best[m][rb], bidx[m][rb], best2[m][rb], dist, code);
                }
        __syncthreads();
    }

    float* redv = (float*)(smem + SM_REDV);
    int*   redi = (int*)(smem + SM_REDI);
    float* red2 = (float*)(smem + SM_RED2);
    #pragma unroll
    for (int m = 0; m < 2; m++)
        #pragma unroll
        for (int rb = 0; rb < 2; rb++) {
            float v1 = best[m][rb], v2 = best2[m][rb];
            int   id = bidx[m][rb];
            #pragma unroll
            for (int off = 1; off <= 2; off <<= 1) {
                float ov1 = __shfl_xor_sync(0xffffffffu, v1, off);
                float ov2 = __shfl_xor_sync(0xffffffffu, v2, off);
                int   oi  = __shfl_xor_sync(0xffffffffu, id, off);
                merge3(v1, id, v2, ov1, oi);
                merge3(v1, id, v2, ov2, 0x7fffffff);
            }
            if (lq == 0) {
                int row = wr * 32 + m * 16 + rb * 8 + lr;
                redv[wc * 128 + row] = v1;
                redi[wc * 128 + row] = id;
                red2[wc * 128 + row] = v2;
            }
        }
    __syncthreads();

    int* s_ft = (int*)(smem + SM_FT);
    int* s_fp = (int*)(smem + SM_FP);
    int* s_nf = (int*)(smem + SM_NF);
    if (tid < 128) {
        float v1 = redv[tid],       s1 = red2[tid];
        float w1 = redv[128 + tid], w2 = red2[128 + tid];
        int   i1 = redi[tid],       j1 = redi[128 + tid];
        merge3(v1, i1, s1, w1, j1);
        merge3(v1, i1, s1, w2, 0x7fffffff);
        int token = ctaM * 128 + tid;
        g_idx[token] = i1;
        if (s1 - v1 < EPS_FLAG) {
            g_fixkey[token] = 0xFFFFFFFFFFFFFFFFull;
            int p = atomicAdd(&g_fixcnt, 1);
            g_fixlist[p] = token;
            int li = atomicAdd(s_nf, 1);
            s_ft[li] = tid;
            s_fp[li] = p;
        }
    }
    __syncthreads();

    // fused gather: each warp copies flagged tokens' z rows into compact g_zfix
    int nf = *s_nf;
    for (int i = w; i < nf; i += 8) {
        int s = s0 + s_ft[i];
        const float* zp = z + (size_t)b * 131072 + s;
        float4 v;
        v.x = zp[(size_t)(l * 4    ) * 1024];
        v.y = zp[(size_t)(l * 4 + 1) * 1024];
        v.z = zp[(size_t)(l * 4 + 2) * 1024];
        v.w = zp[(size_t)(l * 4 + 3) * 1024];
        *(float4*)&g_zfix[(size_t)s_fp[i] * D_DIM + l * 4] = v;
    }
}

// ---------------- exact fp32 recompute: 64 tokens x 32-code half-tile per block ----------------
// thread = 8 tokens x 1 code. u64 atomicMin merge.
__global__ void __launch_bounds__(256) fixup_kernel(const float* __restrict__ cb) {
    extern __shared__ char fsm[];
    float*  ztok = (float*)(fsm + FX_Z);              // [64 tok][128]
    float4* cbt4 = (float4*)(fsm + FX_C);             // [32 code][33 float4]
    float*  cnt_ = (float*)(fsm + FX_N);
    const int tid  = threadIdx.x;
    const int tg   = tid >> 5;                        // 8 token-groups of 8
    const int lane = tid & 31;                        // one code per lane
    const int cnt = g_fixcnt;
    const int nwork = ((cnt + FIX_G - 1) / FIX_G) * 32;

    for (int wi = blockIdx.x; wi < nwork; wi += gridDim.x) {
        int batch = wi >> 5, tile = wi & 31;          // tile = 32-code group
        int base = batch * FIX_G;

        // load 64 compact token rows (coalesced float4)
        for (int u = tid; u < FIX_G * 32; u += 256) {   // 2048 float4 units
            int ti = base + (u >> 5);
            float4 v = make_float4(0.f, 0.f, 0.f, 0.f);
            if (ti < cnt) v = *(const float4*)&g_zfix[(size_t)ti * D_DIM + (u & 31) * 4];
            ((float4*)ztok)[u] = v;
        }
        // load 32-code half-tile + norms
        for (int u = tid; u < 1024; u += 256) {
            cbt4[(u >> 5) * 33 + (u & 31)] =
                ((const float4*)cb)[(size_t)(tile * 32 + (u >> 5)) * 32 + (u & 31)];
        }
        if (tid < 32) cnt_[tid] = g_cnorm[tile * 32 + tid];
        __syncthreads();

        // dots: 8 tokens (tg*8..+7) x 1 code (lane)
        float dot[8];
        #pragma unroll
        for (int t = 0; t < 8; t++) dot[t] = 0.f;
        const float4* zp4 = (const float4*)ztok;
        #pragma unroll 2
        for (int q4 = 0; q4 < 32; q4++) {
            float4 cv = cbt4[lane * 33 + q4];
            #pragma unroll
            for (int t = 0; t < 8; t++) {
                float4 zv = zp4[(tg * 8 + t) * 32 + q4];    // warp-broadcast
                dot[t] = fmaf(zv.x, cv.x, fmaf(zv.y, cv.y,
                         fmaf(zv.z, cv.z, fmaf(zv.w, cv.w, dot[t]))));
            }
        }
        float n0 = cnt_[lane];
        #pragma unroll
        for (int t = 0; t < 8; t++) {
            float d0 = fmaf(-2.f, dot[t], n0);
            unsigned long long key =
                ((unsigned long long)fkey(d0) << 32) | (unsigned)(tile * 32 + lane);
            #pragma unroll
            for (int off = 16; off; off >>= 1) {
                unsigned long long ok = __shfl_xor_sync(0xffffffffu, key, off);
                if (ok < key) key = ok;
            }
            int ti = base + tg * 8 + t;
            if (lane == 0 && ti < cnt)
                atomicMin(&g_fixkey[g_fixlist[ti]], key);
        }
        __syncthreads();
    }
}

// ---------------- writeback: key -> g_idx ----------------
__global__ void __launch_bounds__(256) fixwb_kernel() {
    int cnt = g_fixcnt;
    for (int i = blockIdx.x * blockDim.x + threadIdx.x; i < cnt;
         i += gridDim.x * blockDim.x) {
        int token = g_fixlist[i];
        g_idx[token] = (int)(g_fixkey[token] & 1023u);
    }
}

// ---------------- gather quantized + loss + counts + idx (2 tokens/warp) ----------------
__global__ void __launch_bounds__(256) quant_kernel(const float* __restrict__ z,
                                                    const float* __restrict__ cb,
                                                    float* __restrict__ out) {
    int wid  = threadIdx.x >> 5;
    int lane = threadIdx.x & 31;
    int n0   = blockIdx.x * 16 + wid * 2;

    int k0 = g_idx[n0];
    int k1 = g_idx[n0 + 1];

    float4 q0 = *(const float4*)&cb[k0 * D_DIM + lane * 4];
    float4 q1 = *(const float4*)&cb[k1 * D_DIM + lane * 4];
    size_t o0 = (size_t)n0 * D_DIM + lane * 4;
    float4 z0 = *(const float4*)&z[o0];
    float4 z1 = *(const float4*)&z[o0 + D_DIM];
    *(float4*)&out[Q_OFF + o0]         = q0;
    *(float4*)&out[Q_OFF + o0 + D_DIM] = q1;

    float dx = q0.x - z0.x, dy = q0.y - z0.y, dz = q0.z - z0.z, dw = q0.w - z0.w;
    float s  = dx * dx + dy * dy + dz * dz + dw * dw;
    dx = q1.x - z1.x; dy = q1.y - z1.y; dz = q1.z - z1.z; dw = q1.w - z1.w;
    s += dx * dx + dy * dy + dz * dz + dw * dw;
    #pragma unroll
    for (int o = 16; o; o >>= 1) s += __shfl_xor_sync(0xffffffffu, s, o);

    __shared__ float ws[8];
    if (lane == 0) {
        ws[wid] = s;
        atomicAdd(&g_counts[k0], 1.f);
        atomicAdd(&g_counts[k1], 1.f);
        out[IDX_OFF + n0]     = (float)k0;
        out[IDX_OFF + n0 + 1] = (float)k1;
    }
    __syncthreads();
    if (threadIdx.x == 0) {
        float t = 0.f;
        #pragma unroll
        for (int i = 0; i < 8; i++) t += ws[i];
        atomicAdd(&g_loss, t);
    }
}

// ---------------- dw scatter: vector red.v4 (4 d per thread) ----------------
__global__ void __launch_bounds__(256) dw_kernel(const float* __restrict__ z) {
    int u  = blockIdx.x * blockDim.x + threadIdx.x;   // < 2097152
    int s  = u & 1023;
    int dg = (u >> 10) & 31;
    int b  = u >> 15;
    int n  = (b << 10) + s;
    int k  = g_idx[n];
    const float* zp = z + (size_t)b * 131072 + (size_t)dg * 4096 + s;
    float v0 = zp[0], v1 = zp[1024], v2 = zp[2048], v3 = zp[3072];
    float* dst = &g_dw[k * D_DIM + dg * 4];
    asm volatile("red.global.add.v4.f32 [%0], {%1,%2,%3,%4};"
                 :: "l"(dst), "f"(v0), "f"(v1), "f"(v2), "f"(v3) : "memory");
}

// ---------------- EMA count update + weights + losses ----------------
__global__ void finalize1_kernel(const float* __restrict__ ema_count,
                                 float* __restrict__ out) {
    int k = threadIdx.x;
    float c = EMA * ema_count[k] + (1.f - EMA) * g_counts[k];
    out[CNT_OFF + k] = c;

    __shared__ float sm[1024];
    sm[k] = c;
    __syncthreads();
    for (int o = 512; o; o >>= 1) {
        if (k < o) sm[k] += sm[k + o];
        __syncthreads();
    }
    float n = sm[0];
    g_weights[k] = (c + EPSV) / (n + K_CODES * EPSV) * n;

    if (k == 0) {
        float L = g_loss / 8388608.f;
        out[L_OFF]     = L;
        out[L_OFF + 1] = L;
    }
}

// ---------------- EMA weight update + new codebook ----------------
__global__ void finalize2_kernel(const float* __restrict__ ema_weight,
                                 float* __restrict__ out) {
    int i = blockIdx.x * blockDim.x + threadIdx.x;
    int k = i >> 7;
    float w = EMA * ema_weight[i] + (1.f - EMA) * g_dw[i];
    out[EMW_OFF + i] = w;
    out[CB_OFF + i]  = w / g_weights[k];
}

// ---------------- launch ----------------
extern "C" void kernel_launch(void* const* d_in, const int* in_sizes, int n_in,
                              void* d_out, int out_size) {
    const float* z          = (const float*)d_in[0];
    const float* cb         = (const float*)d_in[1];
    const float* ema_count  = (const float*)d_in[2];
    const float* ema_weight = (const float*)d_in[3];
    float* out = (float*)d_out;

    cudaFuncSetAttribute(argmin_mma_kernel,
                         cudaFuncAttributeMaxDynamicSharedMemorySize, SM_TOTAL);
    cudaFuncSetAttribute(fixup_kernel,
                         cudaFuncAttributeMaxDynamicSharedMemorySize, FX_TOTAL);

    prep_all_kernel<<<K_CODES, 128>>>(cb);
    argmin_mma_kernel<<<N_TOK / 128, 256, SM_TOTAL>>>(z);
    fixup_kernel<<<1024, 256, FX_TOTAL>>>(cb);
    fixwb_kernel<<<16, 256>>>();
    quant_kernel<<<N_TOK / 16, 256>>>(z, cb, out);
    dw_kernel<<<Z_ELEMS / 1024, 256>>>(z);
    finalize1_kernel<<<1, 1024>>>(ema_count, out);
    finalize2_kernel<<<512, 256>>>(ema_weight, out);
}

// round 17
// speedup vs baseline: 1.0317x; 1.0317x over previous
#include <cuda_runtime.h>
#include <cuda_fp16.h>
#include <cstdint>

// ---------------- problem constants ----------------
#define K_CODES   1024
#define D_DIM     128
#define N_TOK     65536        // 64 * 32 * 32 tokens (BHWC order)
#define Z_ELEMS   8388608      // 64 * 128 * 32 * 32
#define EMA       0.99f
#define EPSV      1e-5f
#define EPS_FLAG  0.08f        // approx-gap threshold (4.2 sigma of fp16 pair error)

// ---------------- output layout (flattened reference tuple, fp32) ----------------
#define Q_OFF     0
#define IDX_OFF   8388608
#define L_OFF     8454144
#define CB_OFF    8454146
#define CNT_OFF   8585218
#define EMW_OFF   8586242

// ---------------- smem layout for argmin (bytes) ----------------
#define SM_A      0            // 32KB: A fp16 frag-packed (filled in-kernel)
#define SM_B      32768        // 2 stages * 16KB (also fp32 z staging at start)
#define SM_CN     65536        // 1024 floats
#define SM_REDV   69632
#define SM_REDI   70656
#define SM_RED2   71680
#define SM_TOTAL  72704
#define ZT_STRIDE 132

// ---------------- smem layout for fixup (bytes, dynamic) ----------------
#define FIX_G     64
#define FX_Z      0            // 64 tokens * 128 floats = 32768
#define FX_C      32768        // 64 codes * 33 float4 = 33792
#define FX_N      66560        // 64 floats
#define FX_TOTAL  66816

// ---------------- global scratch ----------------
__device__ uint32_t g_Bh[65536];          // cb fp16 [tile16][s8][np4][lane32][comp4] (256KB)
__device__ float    g_cnorm[K_CODES];
__device__ float    g_counts[K_CODES];
__device__ float    g_dw[K_CODES * D_DIM];
__device__ int      g_idx[N_TOK];
__device__ float    g_loss;
__device__ float    g_weights[K_CODES];
__device__ int      g_fixcnt;
__device__ int      g_fixlist[N_TOK];
__device__ unsigned long long g_fixkey[N_TOK];   // (ordered-dist << 32) | code
__device__ float    g_zfix[N_TOK * D_DIM];       // compact z rows of flagged tokens

// ---------------- helpers ----------------
__device__ __forceinline__ uint32_t smem_u32(const void* p) {
    uint32_t a;
    asm("{ .reg .u64 t; cvta.to.shared.u64 t, %1; cvt.u32.u64 %0, t; }" : "=r"(a) : "l"(p));
    return a;
}
__device__ __forceinline__ uint32_t packh(float a, float b) {
    __half2 t = __floats2half2_rn(a, b);   // x=a (low), y=b (high)
    return *(uint32_t*)&t;
}
__device__ __forceinline__ void mma16(float* c, const uint32_t* a, const uint32_t* b) {
    asm volatile("mma.sync.aligned.m16n8k16.row.col.f32.f16.f16.f32 "
                 "{%0,%1,%2,%3}, {%4,%5,%6,%7}, {%8,%9}, {%0,%1,%2,%3};"
                 : "+f"(c[0]), "+f"(c[1]), "+f"(c[2]), "+f"(c[3])
                 : "r"(a[0]), "r"(a[1]), "r"(a[2]), "r"(a[3]), "r"(b[0]), "r"(b[1]));
}
// screen merge: no index tie-break (exact ties => gap 0 => flagged => fixup decides)
__device__ __forceinline__ void merge3(float& b1, int& i1, float& b2, float v, int id) {
    if (v < b1) { b2 = b1; b1 = v; i1 = id; }
    else if (v < b2) b2 = v;
}
// order-preserving float -> uint32 (monotone for all finite values)
__device__ __forceinline__ uint32_t fkey(float f) {
    uint32_t b = __float_as_uint(f);
    return (b & 0x80000000u) ? ~b : (b | 0x80000000u);
}
#define CP16(dst, src) \
    asm volatile("cp.async.cg.shared.global [%0], [%1], 16;" :: "r"(dst), "l"(src) : "memory")
#define CP_COMMIT() asm volatile("cp.async.commit_group;" ::: "memory")
#define CP_WAIT1()  asm volatile("cp.async.wait_group 1;" ::: "memory")
#define CP_WAIT0()  asm volatile("cp.async.wait_group 0;" ::: "memory")

// ---------------- fused prep: zero + cnorm + fp16 cb fragments ----------------
__global__ void __launch_bounds__(128) prep_all_kernel(const float* __restrict__ cb) {
    const int k = blockIdx.x, d = threadIdx.x;
    float v = cb[k * D_DIM + d];

    g_dw[k * D_DIM + d] = 0.f;
    if (d == 0) g_counts[k] = 0.f;
    if (k == 0 && d == 0) { g_loss = 0.f; g_fixcnt = 0; }

    float vn = __shfl_xor_sync(0xffffffffu, v, 1);

    float sq = v * v;
    #pragma unroll
    for (int o = 16; o; o >>= 1) sq += __shfl_xor_sync(0xffffffffu, sq, o);
    __shared__ float ws[4];
    if ((d & 31) == 0) ws[d >> 5] = sq;
    __syncthreads();
    if (d == 0) g_cnorm[k] = ws[0] + ws[1] + ws[2] + ws[3];

    if ((d & 1) == 0) {
        uint32_t ph = packh(v, vn);
        int tile = k >> 6, c = k & 63;
        int nf = c >> 3, np = nf >> 1, nin = c & 7;
        int s  = d >> 4, dk = d & 15;
        int kb = dk >> 3, lq = (dk & 7) >> 1;
        int lane = nin * 4 + lq;
        int comp = (nf & 1) * 2 + kb;
        g_Bh[(((tile * 8 + s) * 4 + np) * 32 + lane) * 4 + comp] = ph;
    }
}

// ---------------- fp16 screening GEMM + argmin (A converted in-kernel) ----------------
__global__ void __launch_bounds__(256, 2) argmin_mma_kernel(const float* __restrict__ z) {
    extern __shared__ char smem[];
    const uint32_t smb = smem_u32(smem);
    const int tid = threadIdx.x;
    const int l   = tid & 31, w = tid >> 5;
    const int wr  = w & 3,    wc = w >> 2;
    const int lq  = l & 3,    lr = l >> 2;
    const int ctaM = blockIdx.x;
    const int b   = ctaM >> 3;
    const int s0  = (ctaM & 7) << 7;

    // ---- convert z tile -> fp16 A fragments (4 chunks of 32 d, staged in SM_B) ----
    {
        float* zstage = (float*)(smem + SM_B);           // [32 d][ZT_STRIDE]
        const float* zp = z + (size_t)b * 131072 + s0;
        uint4* Adst = (uint4*)(smem + SM_A);
        #pragma unroll
        for (int c = 0; c < 4; c++) {
            #pragma unroll
            for (int j = 0; j < 4; j++) {
                int u = j * 256 + tid;
                int d = u >> 5, t4 = (u & 31) << 2;
                float4 v = *(const float4*)&zp[(size_t)(c * 32 + d) * 1024 + t4];
                *(float4*)&zstage[d * ZT_STRIDE + t4] = v;
            }
            __syncthreads();
            #pragma unroll
            for (int j = 0; j < 2; j++) {
                int u = j * 256 + tid;
                int f = u >> 6, shalf = (u >> 5) & 1, li = u & 31;
                int s = c * 2 + shalf;
                int T0 = f * 16 + (li >> 2);
                int r0 = shalf * 16 + (li & 3) * 2;
                uint32_t rh[4];
                rh[0] = packh(zstage[r0 * ZT_STRIDE + T0],       zstage[(r0 + 1) * ZT_STRIDE + T0]);
                rh[1] = packh(zstage[r0 * ZT_STRIDE + T0 + 8],   zstage[(r0 + 1) * ZT_STRIDE + T0 + 8]);
                rh[2] = packh(zstage[(r0 + 8) * ZT_STRIDE + T0], zstage[(r0 + 9) * ZT_STRIDE + T0]);
                rh[3] = packh(zstage[(r0 + 8) * ZT_STRIDE + T0 + 8], zstage[(r0 + 9) * ZT_STRIDE + T0 + 8]);
                Adst[(f * 8 + s) * 32 + li] = make_uint4(rh[0], rh[1], rh[2], rh[3]);
            }
            __syncthreads();
        }
    }

    {
        CP16(smb + SM_CN + tid * 16, g_cnorm + tid * 4);
        const uint4* bh = (const uint4*)g_Bh;
        #pragma unroll
        for (int j = 0; j < 4; j++) {
            int c = j * 256 + tid;
            CP16(smb + SM_B + c * 16, bh + c);
        }
        CP_COMMIT();
    }

    float acc[2][4][4];
    float best [2][2] = {{3.4e38f, 3.4e38f}, {3.4e38f, 3.4e38f}};
    float best2[2][2] = {{3.4e38f, 3.4e38f}, {3.4e38f, 3.4e38f}};
    int   bidx [2][2] = {{0, 0}, {0, 0}};

    for (int t = 0; t < 16; t++) {
        if (t < 15) {
            const uint4* bh = (const uint4*)g_Bh + (t + 1) * 1024;
            uint32_t dst = smb + SM_B + ((t + 1) & 1) * 16384;
            #pragma unroll
            for (int j = 0; j < 4; j++) {
                int c = j * 256 + tid;
                CP16(dst + c * 16, bh + c);
            }
            CP_COMMIT();
            CP_WAIT1();
        } else {
            CP_WAIT0();
        }
        __syncthreads();

        #pragma unroll
        for (int m = 0; m < 2; m++)
            #pragma unroll
            for (int n = 0; n < 4; n++)
                #pragma unroll
                for (int e = 0; e < 4; e++) acc[m][n][e] = 0.f;

        const uint4* Ah4 = (const uint4*)(smem + SM_A);
        const uint4* Bh4 = (const uint4*)(smem + SM_B + (size_t)(t & 1) * 16384);

        #pragma unroll
        for (int s = 0; s < 8; s++) {
            uint4 A0 = Ah4[((wr * 2 + 0) * 8 + s) * 32 + l];
            uint4 A1 = Ah4[((wr * 2 + 1) * 8 + s) * 32 + l];
            uint4 B0 = Bh4[(s * 4 + wc * 2 + 0) * 32 + l];
            uint4 B1 = Bh4[(s * 4 + wc * 2 + 1) * 32 + l];

            uint32_t ah[2][4] = {{A0.x, A0.y, A0.z, A0.w}, {A1.x, A1.y, A1.z, A1.w}};
            uint32_t bh[4][2] = {{B0.x, B0.y}, {B0.z, B0.w}, {B1.x, B1.y}, {B1.z, B1.w}};

            #pragma unroll
            for (int m = 0; m < 2; m++)
                #pragma unroll
                for (int n = 0; n < 4; n++) mma16(acc[m][n], ah[m], bh[n]);
        }

        const float* cn = (const float*)(smem + SM_CN);
        #pragma unroll
        for (int m = 0; m < 2; m++)
            #pragma unroll
            for (int n = 0; n < 4; n++)
                #pragma unroll
                for (int e = 0; e < 4; e++) {
                    int code = t * 64 + (wc * 4 + n) * 8 + lq * 2 + (e & 1);
                    float dist = fmaf(-2.f, acc[m][n][e], cn[code]);
                    int rb = e >> 1;
                    merge3(best[m][rb], bidx[m][rb], best2[m][rb], dist, code);
                }
        __syncthreads();
    }

    float* redv = (float*)(smem + SM_REDV);
    int*   redi = (int*)(smem + SM_REDI);
    float* red2 = (float*)(smem + SM_RED2);
    #pragma unroll
    for (int m = 0; m < 2; m++)
        #pragma unroll
        for (int rb = 0; rb < 2; rb++) {
            float v1 = best[m][rb], v2 = best2[m][rb];
            int   id = bidx[m][rb];
            #pragma unroll
            for (int off = 1; off <= 2; off <<= 1) {
                float ov1 = __shfl_xor_sync(0xffffffffu, v1, off);
                float ov2 = __shfl_xor_sync(0xffffffffu, v2, off);
                int   oi  = __shfl_xor_sync(0xffffffffu, id, off);
                merge3(v1, id, v2, ov1, oi);
                merge3(v1, id, v2, ov2, 0x7fffffff);
            }
            if (lq == 0) {
                int row = wr * 32 + m * 16 + rb * 8 + lr;
                redv[wc * 128 + row] = v1;
                redi[wc * 128 + row] = id;
                red2[wc * 128 + row] = v2;
            }
        }
    __syncthreads();
    if (tid < 128) {
        float v1 = redv[tid],       s1 = red2[tid];
        float w1 = redv[128 + tid], w2 = red2[128 + tid];
        int   i1 = redi[tid],       j1 = redi[128 + tid];
        merge3(v1, i1, s1, w1, j1);
        merge3(v1, i1, s1, w2, 0x7fffffff);
        int token = ctaM * 128 + tid;
        g_idx[token] = i1;
        if (s1 - v1 < EPS_FLAG) {
            g_fixkey[token] = 0xFFFFFFFFFFFFFFFFull;
            int p = atomicAdd(&g_fixcnt, 1);
            g_fixlist[p] = token;
        }
    }
}

// ---------------- gather flagged tokens' z rows into compact buffer ----------------
__global__ void __launch_bounds__(256) gatherz_kernel(const float* __restrict__ z) {
    const int cnt  = g_fixcnt;
    const int gw   = (blockIdx.x * blockDim.x + threadIdx.x) >> 5;
    const int lane = threadIdx.x & 31;
    const int nw   = (gridDim.x * blockDim.x) >> 5;
    for (int i = gw; i < cnt; i += nw) {
        int token = g_fixlist[i];
        int b = token >> 10, s = token & 1023;
        const float* zp = z + (size_t)b * 131072 + s;
        float4 v;
        v.x = zp[(size_t)(lane * 4    ) * 1024];
        v.y = zp[(size_t)(lane * 4 + 1) * 1024];
        v.z = zp[(size_t)(lane * 4 + 2) * 1024];
        v.w = zp[(size_t)(lane * 4 + 3) * 1024];
        *(float4*)&g_zfix[(size_t)i * D_DIM + lane * 4] = v;
    }
}

// ---------------- exact fp32 recompute: 64 tokens x 64-code tile per block ----------------
// thread = 8 tokens x 2 codes -> FMA-bound. u64 atomicMin merge.
__global__ void __launch_bounds__(256) fixup_kernel(const float* __restrict__ cb) {
    extern __shared__ char fsm[];
    float*  ztok = (float*)(fsm + FX_Z);              // [64 tok][128]
    float4* cbt4 = (float4*)(fsm + FX_C);             // [64 code][33 float4]
    float*  cnt_ = (float*)(fsm + FX_N);
    const int tid  = threadIdx.x;
    const int tg   = tid >> 5;                        // 8 token-groups of 8
    const int lane = tid & 31;                        // code slot: lane, lane+32
    const int cnt = g_fixcnt;
    const int nwork = ((cnt + FIX_G - 1) / FIX_G) * 16;

    for (int wi = blockIdx.x; wi < nwork; wi += gridDim.x) {
        int batch = wi >> 4, tile = wi & 15;
        int base = batch * FIX_G;

        // load 64 compact token rows (coalesced float4)
        for (int u = tid; u < FIX_G * 32; u += 256) {   // 2048 float4 units
            int ti = base + (u >> 5);
            float4 v = make_float4(0.f, 0.f, 0.f, 0.f);
            if (ti < cnt) v = *(const float4*)&g_zfix[(size_t)ti * D_DIM + (u & 31) * 4];
            ((float4*)ztok)[u] = v;
        }
        // load code tile + norms
        for (int u = tid; u < 2048; u += 256) {
            cbt4[(u >> 5) * 33 + (u & 31)] = ((const float4*)cb)[tile * 2048 + u];
        }
        if (tid < 64) cnt_[tid] = g_cnorm[tile * 64 + tid];
        __syncthreads();

        // dots: 8 tokens (tg*8..+7) x 2 codes (lane, lane+32)
        float dot[8][2];
        #pragma unroll
        for (int t = 0; t < 8; t++) { dot[t][0] = 0.f; dot[t][1] = 0.f; }
        const float4* zp4 = (const float4*)ztok;
        #pragma unroll 2
        for (int q4 = 0; q4 < 32; q4++) {
            float4 cv0 = cbt4[lane * 33 + q4];
            float4 cv1 = cbt4[(lane + 32) * 33 + q4];
            #pragma unroll
            for (int t = 0; t < 8; t++) {
                float4 zv = zp4[(tg * 8 + t) * 32 + q4];    // warp-broadcast
                dot[t][0] = fmaf(zv.x, cv0.x, fmaf(zv.y, cv0.y,
                            fmaf(zv.z, cv0.z, fmaf(zv.w, cv0.w, dot[t][0]))));
                dot[t][1] = fmaf(zv.x, cv1.x, fmaf(zv.y, cv1.y,
                            fmaf(zv.z, cv1.z, fmaf(zv.w, cv1.w, dot[t][1]))));
            }
        }
        float n0 = cnt_[lane], n1 = cnt_[lane + 32];
        #pragma unroll
        for (int t = 0; t < 8; t++) {
            float d0 = fmaf(-2.f, dot[t][0], n0);
            float d1 = fmaf(-2.f, dot[t][1], n1);
            unsigned long long key =
                ((unsigned long long)fkey(d0) << 32) | (unsigned)(tile * 64 + lane);
            unsigned long long k2 =
                ((unsigned long long)fkey(d1) << 32) | (unsigned)(tile * 64 + lane + 32);
            if (k2 < key) key = k2;
            #pragma unroll
            for (int off = 16; off; off >>= 1) {
                unsigned long long ok = __shfl_xor_sync(0xffffffffu, key, off);
                if (ok < key) key = ok;
            }
            int ti = base + tg * 8 + t;
            if (lane == 0 && ti < cnt)
                atomicMin(&g_fixkey[g_fixlist[ti]], key);
        }
        __syncthreads();
    }
}

// ---------------- writeback: key -> g_idx ----------------
__global__ void __launch_bounds__(256) fixwb_kernel() {
    int cnt = g_fixcnt;
    for (int i = blockIdx.x * blockDim.x + threadIdx.x; i < cnt;
         i += gridDim.x * blockDim.x) {
        int token = g_fixlist[i];
        g_idx[token] = (int)(g_fixkey[token] & 1023u);
    }
}

// ---------------- gather quantized + loss + counts + idx (2 tokens/warp) ----------------
__global__ void __launch_bounds__(256) quant_kernel(const float* __restrict__ z,
                                                    const float* __restrict__ cb,
                                                    float* __restrict__ out) {
    int wid  = threadIdx.x >> 5;
    int lane = threadIdx.x & 31;
    int n0   = blockIdx.x * 16 + wid * 2;

    int k0 = g_idx[n0];
    int k1 = g_idx[n0 + 1];

    float4 q0 = *(const float4*)&cb[k0 * D_DIM + lane * 4];
    float4 q1 = *(const float4*)&cb[k1 * D_DIM + lane * 4];
    size_t o0 = (size_t)n0 * D_DIM + lane * 4;
    float4 z0 = *(const float4*)&z[o0];
    float4 z1 = *(const float4*)&z[o0 + D_DIM];
    *(float4*)&out[Q_OFF + o0]         = q0;
    *(float4*)&out[Q_OFF + o0 + D_DIM] = q1;

    float dx = q0.x - z0.x, dy = q0.y - z0.y, dz = q0.z - z0.z, dw = q0.w - z0.w;
    float s  = dx * dx + dy * dy + dz * dz + dw * dw;
    dx = q1.x - z1.x; dy = q1.y - z1.y; dz = q1.z - z1.z; dw = q1.w - z1.w;
    s += dx * dx + dy * dy + dz * dz + dw * dw;
    #pragma unroll
    for (int o = 16; o; o >>= 1) s += __shfl_xor_sync(0xffffffffu, s, o);

    __shared__ float ws[8];
    if (lane == 0) {
        ws[wid] = s;
        atomicAdd(&g_counts[k0], 1.f);
        atomicAdd(&g_counts[k1], 1.f);
        out[IDX_OFF + n0]     = (float)k0;
        out[IDX_OFF + n0 + 1] = (float)k1;
    }
    __syncthreads();
    if (threadIdx.x == 0) {
        float t = 0.f;
        #pragma unroll
        for (int i = 0; i < 8; i++) t += ws[i];
        atomicAdd(&g_loss, t);
    }
}

// ---------------- dw scatter: vector red.v4 (4 d per thread) ----------------
__global__ void __launch_bounds__(256) dw_kernel(const float* __restrict__ z) {
    int u  = blockIdx.x * blockDim.x + threadIdx.x;   // < 2097152
    int s  = u & 1023;
    int dg = (u >> 10) & 31;
    int b  = u >> 15;
    int n  = (b << 10) + s;
    int k  = g_idx[n];
    const float* zp = z + (size_t)b * 131072 + (size_t)dg * 4096 + s;
    float v0 = zp[0], v1 = zp[1024], v2 = zp[2048], v3 = zp[3072];
    float* dst = &g_dw[k * D_DIM + dg * 4];
    asm volatile("red.global.add.v4.f32 [%0], {%1,%2,%3,%4};"
                 :: "l"(dst), "f"(v0), "f"(v1), "f"(v2), "f"(v3) : "memory");
}

// ---------------- EMA count update + weights + losses ----------------
__global__ void finalize1_kernel(const float* __restrict__ ema_count,
                                 float* __restrict__ out) {
    int k = threadIdx.x;
    float c = EMA * ema_count[k] + (1.f - EMA) * g_counts[k];
    out[CNT_OFF + k] = c;

    __shared__ float sm[1024];
    sm[k] = c;
    __syncthreads();
    for (int o = 512; o; o >>= 1) {
        if (k < o) sm[k] += sm[k + o];
        __syncthreads();
    }
    float n = sm[0];
    g_weights[k] = (c + EPSV) / (n + K_CODES * EPSV) * n;

    if (k == 0) {
        float L = g_loss / 8388608.f;
        out[L_OFF]     = L;
        out[L_OFF + 1] = L;
    }
}

// ---------------- EMA weight update + new codebook ----------------
__global__ void finalize2_kernel(const float* __restrict__ ema_weight,
                                 float* __restrict__ out) {
    int i = blockIdx.x * blockDim.x + threadIdx.x;
    int k = i >> 7;
    float w = EMA * ema_weight[i] + (1.f - EMA) * g_dw[i];
    out[EMW_OFF + i] = w;
    out[CB_OFF + i]  = w / g_weights[k];
}

// ---------------- launch ----------------
extern "C" void kernel_launch(void* const* d_in, const int* in_sizes, int n_in,
                              void* d_out, int out_size) {
    const float* z          = (const float*)d_in[0];
    const float* cb         = (const float*)d_in[1];
    const float* ema_count  = (const float*)d_in[2];
    const float* ema_weight = (const float*)d_in[3];
    float* out = (float*)d_out;

    cudaFuncSetAttribute(argmin_mma_kernel,
                         cudaFuncAttributeMaxDynamicSharedMemorySize, SM_TOTAL);
    cudaFuncSetAttribute(fixup_kernel,
                         cudaFuncAttributeMaxDynamicSharedMemorySize, FX_TOTAL);

    prep_all_kernel<<<K_CODES, 128>>>(cb);
    argmin_mma_kernel<<<N_TOK / 128, 256, SM_TOTAL>>>(z);
    gatherz_kernel<<<512, 256>>>(z);
    fixup_kernel<<<512, 256, FX_TOTAL>>>(cb);
    fixwb_kernel<<<64, 256>>>();
    quant_kernel<<<N_TOK / 16, 256>>>(z, cb, out);
    dw_kernel<<<Z_ELEMS / 1024, 256>>>(z);
    finalize1_kernel<<<1, 1024>>>(ema_count, out);
    finalize2_kernel<<<512, 256>>>(ema_weight, out);
}